// round 15
// baseline (speedup 1.0000x reference)
#include <cuda_runtime.h>

// Problem constants
#define Bn   64
#define Cn   256
#define Tn   64
#define Vn   25
#define Hn   512
#define TVn  1600      // T*V
#define CTVn 409600    // C*T*V

typedef unsigned long long u64;

// ---------------- packed f32x2 helpers (Blackwell 2x fp32 path) ----------------
__device__ __forceinline__ u64 f2fma(u64 a, u64 b, u64 c){
    u64 d; asm("fma.rn.f32x2 %0,%1,%2,%3;" : "=l"(d) : "l"(a), "l"(b), "l"(c)); return d;
}
__device__ __forceinline__ u64 f2pack(float x, float y){
    u64 d; asm("mov.b64 %0,{%1,%2};" : "=l"(d) : "f"(x), "f"(y)); return d;
}
__device__ __forceinline__ float2 f2unpack(u64 a){
    float2 r; asm("mov.b64 {%0,%1},%2;" : "=f"(r.x), "=f"(r.y) : "l"(a)); return r;
}

// fast tanh: 1 MUFU.EX2 + fast divide; err ~1e-6 rel
__device__ __forceinline__ float ftanh(float x){
    float ax = fabsf(x);
    float e  = __expf(ax + ax);
    float r  = __fdividef(e - 1.0f, e + 1.0f);
    r = (ax > 20.0f) ? 1.0f : r;
    return copysignf(r, x);
}

// Intermediate u = tanh(z W1 + b1), PADDED layout [B][H][28]
__device__ float g_U[Bn * Hn * 28];

// load 7 x ulonglong2 (one padded row: 28 floats) from SMEM
__device__ __forceinline__ void ldz(ulonglong2* q, const u64* row){
    const ulonglong2* p = (const ulonglong2*)row;
    #pragma unroll
    for (int j = 0; j < 7; j++) q[j] = p[j];
}

// 13 packed FMAs: acc[0..12] += q(v-pairs 0..12) * w
__device__ __forceinline__ void fma13(u64* acc, const ulonglong2* q, float wv){
    u64 wp = f2pack(wv, wv);
    acc[0]  = f2fma(q[0].x, wp, acc[0]);
    acc[1]  = f2fma(q[0].y, wp, acc[1]);
    acc[2]  = f2fma(q[1].x, wp, acc[2]);
    acc[3]  = f2fma(q[1].y, wp, acc[3]);
    acc[4]  = f2fma(q[2].x, wp, acc[4]);
    acc[5]  = f2fma(q[2].y, wp, acc[5]);
    acc[6]  = f2fma(q[3].x, wp, acc[6]);
    acc[7]  = f2fma(q[3].y, wp, acc[7]);
    acc[8]  = f2fma(q[4].x, wp, acc[8]);
    acc[9]  = f2fma(q[4].y, wp, acc[9]);
    acc[10] = f2fma(q[5].x, wp, acc[10]);
    acc[11] = f2fma(q[5].y, wp, acc[11]);
    acc[12] = f2fma(q[6].x, wp, acc[12]);
}

// Software-pipelined 256-step K reduction. zrow: padded SMEM rows (14 u64 each),
// rows 0..255 valid, row 256 must be addressable (prefetch target, never consumed).
// w: strided weight column. acc: 13 packed accumulators.
__device__ __forceinline__ void kloop(u64* acc, const u64* zrow,
                                      const float* w, int wstride){
    float wbuf[8];
    #pragma unroll
    for (int i = 0; i < 8; i++) wbuf[i] = w[(size_t)i * wstride];

    ulonglong2 zA[7], zB[7];
    ldz(zA, zrow);

    #pragma unroll 1
    for (int c0 = 0; c0 < 256; c0 += 8){
        float wn[8];
        #pragma unroll
        for (int i = 0; i < 8; i++){
            int cn = c0 + 8 + i;
            wn[i] = (cn < 256) ? w[(size_t)cn * wstride] : 0.0f;
        }
        #pragma unroll
        for (int i = 0; i < 8; i += 2){
            ldz(zB, zrow + (size_t)(c0 + i + 1) * 14);
            fma13(acc, zA, wbuf[i]);
            ldz(zA, zrow + (size_t)(c0 + i + 2) * 14);
            fma13(acc, zB, wbuf[i + 1]);
        }
        #pragma unroll
        for (int i = 0; i < 8; i++) wbuf[i] = wn[i];
    }
}

// ---------------- init: out[:,:,0,:] = h[:,:,0,:] ----------------
__global__ void kinit(const float* __restrict__ h, float* __restrict__ out){
    int idx = blockIdx.x * 256 + threadIdx.x;
    if (idx >= Bn * Cn * Vn) return;
    int v  = idx % Vn;
    int bc = idx / Vn;
    size_t a = (size_t)bc * TVn + v;
    out[a] = h[a];
}

// ---------------- K1: U[b,h,:] = tanh( sum_c z_t[b,c,:] * W1[c,h] + b1[h] ) ----
// grid (4 hblocks, 32 batch-pairs), 256 thr: hl=tid&127, bs=tid>>7.
// SMEM: z tiles [2][257][14] u64 = 57568 B (row 256 = prefetch slack, garbage ok)
__global__ void __launch_bounds__(256, 1) k1(
    const float* __restrict__ hp, const float* __restrict__ outp,
    const float* __restrict__ W1, const float* __restrict__ b1,
    const float* __restrict__ tf, int t)
{
    extern __shared__ u64 zs[];
    int tid = threadIdx.x;
    int bp  = blockIdx.y;
    int hb  = blockIdx.x;

    // stage z_t for the two batches (teacher-forcing select folded in).
    // pad lanes (v=25..27) left as garbage: they only feed discarded accumulators.
    #pragma unroll
    for (int s = 0; s < 2; s++){
        int b = bp * 2 + s;
        float r = tf[t * Bn + b];
        const float* src = (r < 0.5f ? outp : hp) + (size_t)b * CTVn + (size_t)t * Vn;
        float* dst = (float*)(zs + (size_t)s * 257 * 14);
        for (int i = tid; i < 256 * Vn; i += 256){
            int c = i / Vn;
            int v = i - c * Vn;
            dst[c * 28 + v] = src[(size_t)c * TVn + v];
        }
    }
    __syncthreads();

    int hl = tid & 127;
    int bs = tid >> 7;
    int hidx = hb * 128 + hl;

    u64 acc[13];
    {
        float bias = b1[hidx];
        u64 p = f2pack(bias, bias);
        #pragma unroll
        for (int r0 = 0; r0 < 13; r0++) acc[r0] = p;
    }

    kloop(acc, zs + (size_t)bs * 257 * 14, W1 + hidx, Hn);

    // epilogue: tanh + 7x STG.128 into padded g_U row
    float* up = g_U + ((size_t)(bp * 2 + bs) * Hn + hidx) * 28;
    float vals[28];
    #pragma unroll
    for (int r0 = 0; r0 < 13; r0++){
        float2 xy = f2unpack(acc[r0]);
        vals[r0 * 2]     = ftanh(xy.x);
        vals[r0 * 2 + 1] = ftanh(xy.y);
    }
    vals[26] = 0.f; vals[27] = 0.f;
    #pragma unroll
    for (int j = 0; j < 7; j++)
        ((float4*)up)[j] = make_float4(vals[4*j], vals[4*j+1], vals[4*j+2], vals[4*j+3]);
}

// ---------------- K2: out[b,c,t+1,:] = z_t[b,c,:] + b2[c] + sum_h U[b,h,:]*W2[h,c]
// grid (2 cblocks, 64 batches), 256 thr: cl=tid&127, ks=tid>>7 (split-K halves).
// SMEM: U tile [514][14] u64 + combine [128][13] u64 = 70880 B
__global__ void __launch_bounds__(256, 1) k2(
    const float* __restrict__ hp, float* __restrict__ outp,
    const float* __restrict__ W2, const float* __restrict__ b2,
    const float* __restrict__ tf, int t)
{
    extern __shared__ u64 smem[];
    u64* su   = smem;             // [514][14]
    u64* comb = smem + 514 * 14;  // [128][13]

    int tid = threadIdx.x;
    int b   = blockIdx.y;
    int cb  = blockIdx.x;

    // stage padded U[b] (straight float4 copy — same layout)
    {
        const float4* src = (const float4*)(g_U + (size_t)b * Hn * 28);
        float4* dst = (float4*)su;
        #pragma unroll
        for (int j = 0; j < 14; j++)
            dst[tid + j * 256] = src[tid + j * 256];
    }
    __syncthreads();

    int cl = tid & 127;
    int ks = tid >> 7;
    int cidx = cb * 128 + cl;

    u64 acc[13];
    if (ks == 0){
        float bb = b2[cidx];
        u64 p = f2pack(bb, bb);
        #pragma unroll
        for (int r0 = 0; r0 < 13; r0++) acc[r0] = p;
    } else {
        #pragma unroll
        for (int r0 = 0; r0 < 13; r0++) acc[r0] = 0ull;
    }

    kloop(acc, su + (size_t)(ks * 256) * 14, W2 + (size_t)(ks * 256) * Cn + cidx, Cn);

    // split-K combine + residual + store
    if (ks == 1){
        #pragma unroll
        for (int r0 = 0; r0 < 13; r0++) comb[cl * 13 + r0] = acc[r0];
    }
    __syncthreads();
    if (ks == 0){
        float r = tf[t * Bn + b];
        const float* zsrc = (r < 0.5f ? (const float*)outp : hp)
                            + (size_t)b * CTVn + (size_t)cidx * TVn + (size_t)t * Vn;
        float* dst = outp + (size_t)b * CTVn + (size_t)cidx * TVn + (size_t)(t + 1) * Vn;
        #pragma unroll
        for (int r0 = 0; r0 < 13; r0++){
            float2 a0 = f2unpack(acc[r0]);
            float2 a1 = f2unpack(comb[cl * 13 + r0]);
            int v = r0 * 2;
            dst[v] = zsrc[v] + a0.x + a1.x;
            if (v + 1 < Vn) dst[v + 1] = zsrc[v + 1] + a0.y + a1.y;
        }
    }
}

// ---------------- launch ----------------
extern "C" void kernel_launch(void* const* d_in, const int* in_sizes, int n_in,
                              void* d_out, int out_size)
{
    (void)in_sizes; (void)n_in; (void)out_size;
    const float* h  = (const float*)d_in[0];
    const float* W1 = (const float*)d_in[1];
    const float* b1 = (const float*)d_in[2];
    const float* W2 = (const float*)d_in[3];
    const float* b2 = (const float*)d_in[4];
    const float* tf = (const float*)d_in[5];
    float* out = (float*)d_out;

    cudaFuncSetAttribute(k1, cudaFuncAttributeMaxDynamicSharedMemorySize, 57568);
    cudaFuncSetAttribute(k2, cudaFuncAttributeMaxDynamicSharedMemorySize, 70880);

    kinit<<<(Bn * Cn * Vn + 255) / 256, 256>>>(h, out);
    for (int t = 0; t < Tn - 1; t++){
        k1<<<dim3(4, 32), 256, 57568>>>(h, out, W1, b1, tf, t);
        k2<<<dim3(2, 64), 256, 70880>>>(h, out, W2, b2, tf, t);
    }
}

// round 16
// speedup vs baseline: 1.0726x; 1.0726x over previous
#include <cuda_runtime.h>

// Problem constants
#define Bn   64
#define Cn   256
#define Tn   64
#define Vn   25
#define Hn   512
#define TVn  1600      // T*V
#define CTVn 409600    // C*T*V

typedef unsigned long long u64;

// ---------------- packed f32x2 helpers (Blackwell 2x fp32 path) ----------------
__device__ __forceinline__ u64 f2fma(u64 a, u64 b, u64 c){
    u64 d; asm("fma.rn.f32x2 %0,%1,%2,%3;" : "=l"(d) : "l"(a), "l"(b), "l"(c)); return d;
}
__device__ __forceinline__ u64 f2add(u64 a, u64 b){
    u64 d; asm("add.rn.f32x2 %0,%1,%2;" : "=l"(d) : "l"(a), "l"(b)); return d;
}
__device__ __forceinline__ u64 f2pack(float x, float y){
    u64 d; asm("mov.b64 %0,{%1,%2};" : "=l"(d) : "f"(x), "f"(y)); return d;
}
__device__ __forceinline__ float2 f2unpack(u64 a){
    float2 r; asm("mov.b64 {%0,%1},%2;" : "=f"(r.x), "=f"(r.y) : "l"(a)); return r;
}

// fast tanh: 1 MUFU.EX2 + fast divide; err ~1e-6 rel
__device__ __forceinline__ float ftanh(float x){
    float ax = fabsf(x);
    float e  = __expf(ax + ax);
    float r  = __fdividef(e - 1.0f, e + 1.0f);
    r = (ax > 20.0f) ? 1.0f : r;
    return copysignf(r, x);
}

// Intermediate u = tanh(z W1 + b1), PADDED layout [B][H][28]
__device__ float g_U[Bn * Hn * 28];

// load 7 x ulonglong2 (one padded row: 28 floats) from SMEM — full-warp broadcast
__device__ __forceinline__ void ldz(ulonglong2* q, const u64* row){
    const ulonglong2* p = (const ulonglong2*)row;
    #pragma unroll
    for (int j = 0; j < 7; j++) q[j] = p[j];
}

// 13 packed FMAs: acc[0..12] += q(v-pairs 0..12) * w
__device__ __forceinline__ void fma13(u64* acc, const ulonglong2* q, float wv){
    u64 wp = f2pack(wv, wv);
    acc[0]  = f2fma(q[0].x, wp, acc[0]);
    acc[1]  = f2fma(q[0].y, wp, acc[1]);
    acc[2]  = f2fma(q[1].x, wp, acc[2]);
    acc[3]  = f2fma(q[1].y, wp, acc[3]);
    acc[4]  = f2fma(q[2].x, wp, acc[4]);
    acc[5]  = f2fma(q[2].y, wp, acc[5]);
    acc[6]  = f2fma(q[3].x, wp, acc[6]);
    acc[7]  = f2fma(q[3].y, wp, acc[7]);
    acc[8]  = f2fma(q[4].x, wp, acc[8]);
    acc[9]  = f2fma(q[4].y, wp, acc[9]);
    acc[10] = f2fma(q[5].x, wp, acc[10]);
    acc[11] = f2fma(q[5].y, wp, acc[11]);
    acc[12] = f2fma(q[6].x, wp, acc[12]);
}

// Software-pipelined 128-step K reduction (half-K). zrow: padded SMEM rows
// (14 u64 each); rows 0..127 consumed, row 128 must be addressable (prefetch
// target, never consumed). w: strided weight column (already offset to row 0).
__device__ __forceinline__ void kloop128(u64* acc, const u64* zrow,
                                         const float* w, int wstride){
    float wbuf[8];
    #pragma unroll
    for (int i = 0; i < 8; i++) wbuf[i] = w[(size_t)i * wstride];

    ulonglong2 zA[7], zB[7];
    ldz(zA, zrow);

    #pragma unroll 1
    for (int c0 = 0; c0 < 128; c0 += 8){
        float wn[8];
        #pragma unroll
        for (int i = 0; i < 8; i++){
            int cn = c0 + 8 + i;
            wn[i] = (cn < 128) ? w[(size_t)cn * wstride] : 0.0f;
        }
        #pragma unroll
        for (int i = 0; i < 8; i += 2){
            ldz(zB, zrow + (size_t)(c0 + i + 1) * 14);
            fma13(acc, zA, wbuf[i]);
            ldz(zA, zrow + (size_t)(c0 + i + 2) * 14);
            fma13(acc, zB, wbuf[i + 1]);
        }
        #pragma unroll
        for (int i = 0; i < 8; i++) wbuf[i] = wn[i];
    }
}

// ---------------- init: out[:,:,0,:] = h[:,:,0,:] ----------------
__global__ void kinit(const float* __restrict__ h, float* __restrict__ out){
    int idx = blockIdx.x * 256 + threadIdx.x;
    if (idx >= Bn * Cn * Vn) return;
    int v  = idx % Vn;
    int bc = idx / Vn;
    size_t a = (size_t)bc * TVn + v;
    out[a] = h[a];
}

// ---------------- K1: U[b,h,:] = tanh( sum_c z_t[b,c,:] * W1[c,h] + b1[h] ) ----
// grid (4 hblocks, 32 batch-pairs), 512 thr:
//   hl = tid&127, bs = (tid>>7)&1 (batch in pair), ks = tid>>8 (K half)
// SMEM: z tiles [2][257][14] u64 (57568 B) + combine [2][128][13] u64 (26624 B)
__global__ void __launch_bounds__(512, 1) k1(
    const float* __restrict__ hp, const float* __restrict__ outp,
    const float* __restrict__ W1, const float* __restrict__ b1,
    const float* __restrict__ tf, int t)
{
    extern __shared__ u64 zs[];
    u64* comb = zs + 2 * 257 * 14;   // [2][128][13]

    int tid = threadIdx.x;
    int bp  = blockIdx.y;
    int hb  = blockIdx.x;

    // stage z_t for the two batches (teacher-forcing select folded in).
    // pad lanes (v=25..27) left garbage: they only feed discarded accumulators.
    #pragma unroll
    for (int s = 0; s < 2; s++){
        int b = bp * 2 + s;
        float r = tf[t * Bn + b];
        const float* src = (r < 0.5f ? outp : hp) + (size_t)b * CTVn + (size_t)t * Vn;
        float* dst = (float*)(zs + (size_t)s * 257 * 14);
        for (int i = tid; i < 256 * Vn; i += 512){
            int c = i / Vn;
            int v = i - c * Vn;
            dst[c * 28 + v] = src[(size_t)c * TVn + v];
        }
    }
    __syncthreads();

    int hl = tid & 127;
    int bs = (tid >> 7) & 1;
    int ks = tid >> 8;
    int hidx = hb * 128 + hl;

    u64 acc[13];
    if (ks == 0){
        float bias = b1[hidx];
        u64 p = f2pack(bias, bias);
        #pragma unroll
        for (int r0 = 0; r0 < 13; r0++) acc[r0] = p;
    } else {
        #pragma unroll
        for (int r0 = 0; r0 < 13; r0++) acc[r0] = 0ull;
    }

    kloop128(acc,
             zs + (size_t)bs * 257 * 14 + (size_t)ks * 128 * 14,
             W1 + hidx + (size_t)(ks * 128) * Hn, Hn);

    // split-K combine
    if (ks == 1){
        u64* cp = comb + ((size_t)bs * 128 + hl) * 13;
        #pragma unroll
        for (int r0 = 0; r0 < 13; r0++) cp[r0] = acc[r0];
    }
    __syncthreads();
    if (ks == 0){
        const u64* cp = comb + ((size_t)bs * 128 + hl) * 13;
        float* up = g_U + ((size_t)(bp * 2 + bs) * Hn + hidx) * 28;
        float vals[28];
        #pragma unroll
        for (int r0 = 0; r0 < 13; r0++){
            float2 xy = f2unpack(f2add(acc[r0], cp[r0]));
            vals[r0 * 2]     = ftanh(xy.x);
            vals[r0 * 2 + 1] = ftanh(xy.y);
        }
        vals[26] = 0.f; vals[27] = 0.f;
        #pragma unroll
        for (int j = 0; j < 7; j++)
            ((float4*)up)[j] = make_float4(vals[4*j], vals[4*j+1], vals[4*j+2], vals[4*j+3]);
    }
}

// ---------------- K2: out[b,c,t+1,:] = z_t[b,c,:] + b2[c] + sum_h U[b,h,:]*W2[h,c]
// grid (2 cblocks, 64 batches), 512 thr: cl = tid&127, ks = tid>>7 (K quarter).
// SMEM: U tile [514][14] u64 (57568 B) + combine [3][128][13] u64 (39936 B)
__global__ void __launch_bounds__(512, 1) k2(
    const float* __restrict__ hp, float* __restrict__ outp,
    const float* __restrict__ W2, const float* __restrict__ b2,
    const float* __restrict__ tf, int t)
{
    extern __shared__ u64 smem[];
    u64* su   = smem;             // [514][14]
    u64* comb = smem + 514 * 14;  // [3][128][13]

    int tid = threadIdx.x;
    int b   = blockIdx.y;
    int cb  = blockIdx.x;

    // stage padded U[b] (straight float4 copy — identical layout)
    {
        const float4* src = (const float4*)(g_U + (size_t)b * Hn * 28);
        float4* dst = (float4*)su;
        #pragma unroll
        for (int j = 0; j < 7; j++)
            dst[tid + j * 512] = src[tid + j * 512];
    }
    __syncthreads();

    int cl = tid & 127;
    int ks = tid >> 7;            // 0..3, each handles 128 h rows
    int cidx = cb * 128 + cl;

    u64 acc[13];
    if (ks == 0){
        float bb = b2[cidx];
        u64 p = f2pack(bb, bb);
        #pragma unroll
        for (int r0 = 0; r0 < 13; r0++) acc[r0] = p;
    } else {
        #pragma unroll
        for (int r0 = 0; r0 < 13; r0++) acc[r0] = 0ull;
    }

    kloop128(acc,
             su + (size_t)(ks * 128) * 14,
             W2 + cidx + (size_t)(ks * 128) * Cn, Cn);

    // split-K combine (3 writers, ks==0 reduces) + residual + store
    if (ks != 0){
        u64* cp = comb + (((size_t)(ks - 1) * 128) + cl) * 13;
        #pragma unroll
        for (int r0 = 0; r0 < 13; r0++) cp[r0] = acc[r0];
    }
    __syncthreads();
    if (ks == 0){
        const u64* c1 = comb + (size_t)cl * 13;
        const u64* c2 = comb + ((size_t)128 + cl) * 13;
        const u64* c3 = comb + ((size_t)256 + cl) * 13;
        float r = tf[t * Bn + b];
        const float* zsrc = (r < 0.5f ? (const float*)outp : hp)
                            + (size_t)b * CTVn + (size_t)cidx * TVn + (size_t)t * Vn;
        float* dst = outp + (size_t)b * CTVn + (size_t)cidx * TVn + (size_t)(t + 1) * Vn;
        #pragma unroll
        for (int r0 = 0; r0 < 13; r0++){
            u64 s = f2add(f2add(acc[r0], c1[r0]), f2add(c2[r0], c3[r0]));
            float2 a = f2unpack(s);
            int v = r0 * 2;
            dst[v] = zsrc[v] + a.x;
            if (v + 1 < Vn) dst[v + 1] = zsrc[v + 1] + a.y;
        }
    }
}

// ---------------- launch ----------------
extern "C" void kernel_launch(void* const* d_in, const int* in_sizes, int n_in,
                              void* d_out, int out_size)
{
    (void)in_sizes; (void)n_in; (void)out_size;
    const float* h  = (const float*)d_in[0];
    const float* W1 = (const float*)d_in[1];
    const float* b1 = (const float*)d_in[2];
    const float* W2 = (const float*)d_in[3];
    const float* b2 = (const float*)d_in[4];
    const float* tf = (const float*)d_in[5];
    float* out = (float*)d_out;

    const int SM1 = 2 * 257 * 14 * 8 + 2 * 128 * 13 * 8;   // 84192
    const int SM2 = 514 * 14 * 8 + 3 * 128 * 13 * 8;       // 97504
    cudaFuncSetAttribute(k1, cudaFuncAttributeMaxDynamicSharedMemorySize, SM1);
    cudaFuncSetAttribute(k2, cudaFuncAttributeMaxDynamicSharedMemorySize, SM2);

    kinit<<<(Bn * Cn * Vn + 255) / 256, 256>>>(h, out);
    for (int t = 0; t < Tn - 1; t++){
        k1<<<dim3(4, 32), 512, SM1>>>(h, out, W1, b1, tf, t);
        k2<<<dim3(2, 64), 512, SM2>>>(h, out, W2, b2, tf, t);
    }
}